// round 1
// baseline (speedup 1.0000x reference)
#include <cuda_runtime.h>
#include <cuda_bf16.h>
#include <math.h>
#include <float.h>

// Problem constants
#define BB 4
#define SS 2048
#define DD 1024
#define HH 16
#define DK 64
#define ALPHA 0.7f
#define OMALPHA 0.3f

// Scratch (device globals; allocation-free per harness rules)
__device__ float g_Q[BB * SS * DD];
__device__ float g_K[BB * SS * DD];
__device__ float g_V[BB * SS * DD];
__device__ float g_stats[BB * DD * 5];   // A0, A1c, A1s, A2c, A2s per (b,d)
__device__ int   g_anymaskzero;

// ---------------------------------------------------------------------------
// Kernel 0: zero scratch stats + mask flag
// ---------------------------------------------------------------------------
__global__ void zero_scratch_kernel() {
    int i = blockIdx.x * blockDim.x + threadIdx.x;
    if (i < BB * DD * 5) g_stats[i] = 0.0f;
    if (i == 0) g_anymaskzero = 0;
}

// ---------------------------------------------------------------------------
// Kernel 1: Fourier stats. low-pass = projection onto freq bins 0,1,2.
// grid (16 s-chunks, 4 batches), 256 threads. Coalesced over d.
// ---------------------------------------------------------------------------
__global__ void fourier_stats_kernel(const float* __restrict__ x) {
    const int b = blockIdx.y;
    const int sc = blockIdx.x;
    const int tid = threadIdx.x;
    const float w0 = 6.283185307179586476925286766559f / (float)SS;

    float acc[4][5];
#pragma unroll
    for (int i = 0; i < 4; i++)
#pragma unroll
        for (int k = 0; k < 5; k++) acc[i][k] = 0.0f;

    for (int si = 0; si < SS / 16; si++) {
        const int s = sc * (SS / 16) + si;
        float s1, c1;
        sincosf(w0 * (float)s, &s1, &c1);
        const float c2 = c1 * c1 - s1 * s1;
        const float s2 = 2.0f * s1 * c1;
        const float* xp = x + ((size_t)(b * SS + s)) * DD + tid;
#pragma unroll
        for (int i = 0; i < 4; i++) {
            const float v = xp[i * 256];
            acc[i][0] += v;
            acc[i][1] += v * c1;
            acc[i][2] += v * s1;
            acc[i][3] += v * c2;
            acc[i][4] += v * s2;
        }
    }
#pragma unroll
    for (int i = 0; i < 4; i++) {
        const int d = i * 256 + tid;
        float* st = &g_stats[(b * DD + d) * 5];
        atomicAdd(&st[0], acc[i][0]);
        atomicAdd(&st[1], acc[i][1]);
        atomicAdd(&st[2], acc[i][2]);
        atomicAdd(&st[3], acc[i][3]);
        atomicAdd(&st[4], acc[i][4]);
    }
}

// ---------------------------------------------------------------------------
// Kernel 2: mask scan — set flag if any zero exists
// ---------------------------------------------------------------------------
__global__ void mask_scan_kernel(const int* __restrict__ mask, int n) {
    int i = blockIdx.x * blockDim.x + threadIdx.x;
    const int stride = gridDim.x * blockDim.x;
    bool z = false;
    for (; i < n; i += stride)
        if (mask[i] == 0) z = true;
    if (z) atomicExch(&g_anymaskzero, 1);
}

// ---------------------------------------------------------------------------
// Kernel 3: DSP branch + LayerNorm, writes ALPHA*dsp into out.
// grid = B*S blocks, 256 threads (d).
// ---------------------------------------------------------------------------
__global__ void dsp_ln_kernel(const float* __restrict__ x,
                              const float* __restrict__ sqrt_beta,
                              const float* __restrict__ gamma,
                              const float* __restrict__ lnb,
                              float* __restrict__ out) {
    const int bt = blockIdx.x;
    const int b = bt >> 11;
    const int t = bt & (SS - 1);
    const int tid = threadIdx.x;
    const float w0 = 6.283185307179586476925286766559f / (float)SS;

    float s1, c1;
    sincosf(w0 * (float)t, &s1, &c1);
    const float c2 = c1 * c1 - s1 * s1;
    const float s2 = 2.0f * s1 * c1;

    float y[4];
    float sum = 0.0f, sq = 0.0f;
#pragma unroll
    for (int i = 0; i < 4; i++) {
        const int d = i * 256 + tid;
        const float* st = &g_stats[(b * DD + d) * 5];
        const float lp = (st[0] + 2.0f * (st[1] * c1 + st[2] * s1)
                                + 2.0f * (st[3] * c2 + st[4] * s2)) * (1.0f / (float)SS);
        const float v = x[((size_t)(b * SS + t)) * DD + d];
        const float be = sqrt_beta[d];
        const float b2 = be * be;
        const float yy = (1.0f + b2) * v + (1.0f - b2) * lp;
        y[i] = yy;
        sum += yy;
        sq += yy * yy;
    }

    __shared__ float red[18];
#pragma unroll
    for (int o = 16; o; o >>= 1) {
        sum += __shfl_down_sync(0xffffffffu, sum, o);
        sq  += __shfl_down_sync(0xffffffffu, sq, o);
    }
    const int w = tid >> 5, ln = tid & 31;
    if (ln == 0) { red[w] = sum; red[w + 8] = sq; }
    __syncthreads();
    if (tid == 0) {
        float s = 0.0f, ssq = 0.0f;
        for (int i = 0; i < 8; i++) { s += red[i]; ssq += red[i + 8]; }
        red[16] = s; red[17] = ssq;
    }
    __syncthreads();
    sum = red[16]; sq = red[17];

    const float mu = sum * (1.0f / (float)DD);
    const float var = sq * (1.0f / (float)DD) - mu * mu;
    const float rs = rsqrtf(var + 1e-12f);
#pragma unroll
    for (int i = 0; i < 4; i++) {
        const int d = i * 256 + tid;
        out[((size_t)(b * SS + t)) * DD + d] =
            ALPHA * ((y[i] - mu) * rs * gamma[d] + lnb[d]);
    }
}

// ---------------------------------------------------------------------------
// Kernel 4: QKV GEMM. C[m,n] = sum_k X[m,k]*W[n,k] + bias[n].
// Classic 128x128x8 tile, 256 threads, 8x8 per thread. blockIdx.z selects QKV.
// ---------------------------------------------------------------------------
__global__ __launch_bounds__(256) void gemm_qkv_kernel(
    const float* __restrict__ X,
    const float* __restrict__ qw, const float* __restrict__ qb,
    const float* __restrict__ kw, const float* __restrict__ kb,
    const float* __restrict__ vw, const float* __restrict__ vb) {
    const float* W; const float* bias; float* out;
    if (blockIdx.z == 0)      { W = qw; bias = qb; out = g_Q; }
    else if (blockIdx.z == 1) { W = kw; bias = kb; out = g_K; }
    else                      { W = vw; bias = vb; out = g_V; }

    __shared__ float As[8][128];
    __shared__ float Bs[8][128];

    const int tid = threadIdx.x;
    const int m0 = blockIdx.y * 128;
    const int n0 = blockIdx.x * 128;
    const int tx = tid & 15, ty = tid >> 4;

    float acc[8][8];
#pragma unroll
    for (int i = 0; i < 8; i++)
#pragma unroll
        for (int j = 0; j < 8; j++) acc[i][j] = 0.0f;

    const int arow = tid >> 1;
    const int acol = (tid & 1) * 4;
    const float* Aptr = X + ((size_t)(m0 + arow)) * DD + acol;
    const float* Bptr = W + ((size_t)(n0 + arow)) * DD + acol;

    for (int k0 = 0; k0 < DD; k0 += 8) {
        const float4 av = *(const float4*)(Aptr + k0);
        const float4 bv = *(const float4*)(Bptr + k0);
        __syncthreads();
        As[acol + 0][arow] = av.x; As[acol + 1][arow] = av.y;
        As[acol + 2][arow] = av.z; As[acol + 3][arow] = av.w;
        Bs[acol + 0][arow] = bv.x; Bs[acol + 1][arow] = bv.y;
        Bs[acol + 2][arow] = bv.z; Bs[acol + 3][arow] = bv.w;
        __syncthreads();
#pragma unroll
        for (int k = 0; k < 8; k++) {
            float a[8], bb[8];
            *(float4*)&a[0] = *(const float4*)&As[k][ty * 8];
            *(float4*)&a[4] = *(const float4*)&As[k][ty * 8 + 4];
            *(float4*)&bb[0] = *(const float4*)&Bs[k][tx * 8];
            *(float4*)&bb[4] = *(const float4*)&Bs[k][tx * 8 + 4];
#pragma unroll
            for (int i = 0; i < 8; i++)
#pragma unroll
                for (int j = 0; j < 8; j++)
                    acc[i][j] = fmaf(a[i], bb[j], acc[i][j]);
        }
    }

    float bvreg[8];
#pragma unroll
    for (int j = 0; j < 8; j++) bvreg[j] = bias[n0 + tx * 8 + j];

#pragma unroll
    for (int i = 0; i < 8; i++) {
        float* op = out + ((size_t)(m0 + ty * 8 + i)) * DD + n0 + tx * 8;
        float4 r0, r1;
        r0.x = acc[i][0] + bvreg[0]; r0.y = acc[i][1] + bvreg[1];
        r0.z = acc[i][2] + bvreg[2]; r0.w = acc[i][3] + bvreg[3];
        r1.x = acc[i][4] + bvreg[4]; r1.y = acc[i][5] + bvreg[5];
        r1.z = acc[i][6] + bvreg[6]; r1.w = acc[i][7] + bvreg[7];
        *(float4*)op = r0;
        *(float4*)(op + 4) = r1;
    }
}

// ---------------------------------------------------------------------------
// Kernel 5: flash attention (fp32), adds (1-ALPHA)*gsp into out.
// grid (S/128, B*H). 128 threads, 1 query row per thread.
// q[64], O[64] in registers; K/V tiles (64 keys) broadcast from smem.
// ---------------------------------------------------------------------------
__global__ __launch_bounds__(128) void attn_kernel(const int* __restrict__ mask,
                                                   float* __restrict__ out) {
    const int qt = blockIdx.x;
    const int bh = blockIdx.y;
    const int b = bh >> 4, h = bh & 15;
    const int tid = threadIdx.x;
    const int qrow = qt * 128 + tid;

    __shared__ float sK[64 * 64];
    __shared__ float sV[64 * 64];

    float q[64];
    const float* qp = g_Q + ((size_t)(b * SS + qrow)) * DD + h * DK;
#pragma unroll
    for (int k4 = 0; k4 < 16; k4++)
        *(float4*)&q[k4 * 4] = *(const float4*)(qp + k4 * 4);

    float O[64];
#pragma unroll
    for (int k = 0; k < 64; k++) O[k] = 0.0f;
    float m = -FLT_MAX;
    float l = 0.0f;

    const int anyzero = g_anymaskzero;
    const int* mrow = mask + (size_t)qrow * SS;

    for (int kt = 0; kt < SS / 64; kt++) {
        const int j0 = kt * 64;
#pragma unroll
        for (int i = 0; i < 8; i++) {
            const int idx4 = tid + 128 * i;       // 0..1023 float4 slots
            const int r = idx4 >> 4;
            const int kq = (idx4 & 15) * 4;
            *(float4*)&sK[r * 64 + kq] =
                *(const float4*)(g_K + ((size_t)(b * SS + j0 + r)) * DD + h * DK + kq);
            *(float4*)&sV[r * 64 + kq] =
                *(const float4*)(g_V + ((size_t)(b * SS + j0 + r)) * DD + h * DK + kq);
        }
        __syncthreads();

        for (int j = 0; j < 64; j++) {
            bool ok = true;
            if (anyzero) ok = (mrow[j0 + j] != 0);
            float s = 0.0f;
            const float* kj = &sK[j * 64];
#pragma unroll
            for (int k4 = 0; k4 < 16; k4++) {
                const float4 kv = *(const float4*)(kj + k4 * 4);
                s = fmaf(q[k4 * 4 + 0], kv.x, s);
                s = fmaf(q[k4 * 4 + 1], kv.y, s);
                s = fmaf(q[k4 * 4 + 2], kv.z, s);
                s = fmaf(q[k4 * 4 + 3], kv.w, s);
            }
            if (ok) {
                s *= 0.125f;  // 1/sqrt(64)
                float p;
                if (s > m) {
                    const float corr = __expf(m - s);
                    l *= corr;
#pragma unroll
                    for (int k = 0; k < 64; k++) O[k] *= corr;
                    m = s;
                    p = 1.0f;
                } else {
                    p = __expf(s - m);
                }
                l += p;
                const float* vj = &sV[j * 64];
#pragma unroll
                for (int k4 = 0; k4 < 16; k4++) {
                    const float4 vv = *(const float4*)(vj + k4 * 4);
                    O[k4 * 4 + 0] = fmaf(p, vv.x, O[k4 * 4 + 0]);
                    O[k4 * 4 + 1] = fmaf(p, vv.y, O[k4 * 4 + 1]);
                    O[k4 * 4 + 2] = fmaf(p, vv.z, O[k4 * 4 + 2]);
                    O[k4 * 4 + 3] = fmaf(p, vv.w, O[k4 * 4 + 3]);
                }
            }
        }
        __syncthreads();
    }

    const float invl = (l > 0.0f) ? (1.0f / l) : 0.0f;
    float* op = out + ((size_t)(b * SS + qrow)) * DD + h * DK;
#pragma unroll
    for (int k = 0; k < 64; k++)
        op[k] = op[k] + OMALPHA * O[k] * invl;
}

// ---------------------------------------------------------------------------
extern "C" void kernel_launch(void* const* d_in, const int* in_sizes, int n_in,
                              void* d_out, int out_size) {
    const float* x       = (const float*)d_in[0];
    const int*   mask    = (const int*)d_in[1];
    const float* sb      = (const float*)d_in[2];
    const float* gamma   = (const float*)d_in[3];
    const float* lnb     = (const float*)d_in[4];
    const float* qw      = (const float*)d_in[5];
    const float* qb      = (const float*)d_in[6];
    const float* kw      = (const float*)d_in[7];
    const float* kb      = (const float*)d_in[8];
    const float* vw      = (const float*)d_in[9];
    const float* vb      = (const float*)d_in[10];
    float* out = (float*)d_out;
    const int maskN = in_sizes[1];

    zero_scratch_kernel<<<(BB * DD * 5 + 255) / 256, 256>>>();
    fourier_stats_kernel<<<dim3(16, BB), 256>>>(x);
    mask_scan_kernel<<<512, 256>>>(mask, maskN);
    dsp_ln_kernel<<<BB * SS, 256>>>(x, sb, gamma, lnb, out);
    gemm_qkv_kernel<<<dim3(DD / 128, BB * SS / 128, 3), 256>>>(x, qw, qb, kw, kb, vw, vb);
    attn_kernel<<<dim3(SS / 128, BB * HH), 128>>>(mask, out);
}